// round 10
// baseline (speedup 1.0000x reference)
#include <cuda_runtime.h>
#include <cuda_bf16.h>
#include <math.h>
#include <stdint.h>

typedef unsigned long long ull;

// ---------------------------------------------------------------------------
// Problem dims (fixed by the dataset)
// ---------------------------------------------------------------------------
#define B_  16
#define T_  1024
#define D_  8704
#define R_  256
#define H_  72
#define TH3 (3 * H_)   // 216
#define TAU 12
#define BT_ (B_ * T_)

// GEMM1 tiling / unit schedule
#define G1_BK   16
#define KQ_     8                       // k-split factor
#define UCHUNK  (D_ / G1_BK / KQ_)      // 68 chunks per unit
#define NUNITS  (128 * KQ_)             // 1024
#define GRID1   148                     // persistent CTAs (1/SM)
#define G1_STAGE_FLOATS (G1_BK * 128 + G1_BK * 256)   // 6144
#define G1_STAGE_BYTES  (G1_STAGE_FLOATS * 4)         // 24576
#define G1_DYN  (2 * G1_STAGE_BYTES)                  // 49152 = 48KB

// GEMM2
#define G2_NCH  (R_ / G1_BK)            // 16

// ---------------------------------------------------------------------------
// Scratch (no cudaMalloc allowed -> __device__ globals)
// ---------------------------------------------------------------------------
__device__ float g_part[KQ_][BT_ * R_];     // 134MB split-K partials
__device__ float g_xr[BT_ * R_];            // [B*T, R]
__device__ float g_xp[BT_ * TH3];           // [B*T, 3H]
__device__ float g_hseq[BT_ * H_];          // [B*T, H] GRU hidden history
__device__ float g_q [BT_];                 // [B, T]

// ---------------------------------------------------------------------------
// f32x2 packed helpers
// ---------------------------------------------------------------------------
__device__ __forceinline__ uint32_t smem_u32(const void* p) {
    uint32_t a;
    asm("{ .reg .u64 t; cvta.to.shared.u64 t, %1; cvt.u32.u64 %0, t; }"
        : "=r"(a) : "l"(p));
    return a;
}

__device__ __forceinline__ ull ffma2(ull a, ull b, ull c) {
    ull d;
    asm("fma.rn.f32x2 %0, %1, %2, %3;" : "=l"(d) : "l"(a), "l"(b), "l"(c));
    return d;
}

__device__ __forceinline__ ull fadd2(ull a, ull b) {
    ull d;
    asm("add.rn.f32x2 %0, %1, %2;" : "=l"(d) : "l"(a), "l"(b));
    return d;
}

__device__ __forceinline__ ull dupf(float f) {
    ull d;
    asm("mov.b64 %0, {%1, %1};" : "=l"(d) : "r"(__float_as_uint(f)));
    return d;
}

__device__ __forceinline__ ull packf(float lo, float hi) {
    ull d;
    asm("mov.b64 %0, {%1, %2};" : "=l"(d)
        : "r"(__float_as_uint(lo)), "r"(__float_as_uint(hi)));
    return d;
}

__device__ __forceinline__ float f2lo(ull u) {
    return __uint_as_float((uint32_t)u);
}
__device__ __forceinline__ float f2hi(ull u) {
    return __uint_as_float((uint32_t)(u >> 32));
}

__device__ __forceinline__ float tanh_fast(float x) {
    float y;
    asm("tanh.approx.f32 %0, %1;" : "=f"(y) : "f"(x));
    return y;
}

// ---------------------------------------------------------------------------
// GEMM1 (split-K persistent): part[kq][m,n] = x[m, kq-slice] @ w_dr^T
// ---------------------------------------------------------------------------
__global__ __launch_bounds__(256, 1)
void gemm1_f2_kernel(const float* __restrict__ A,
                     const float* __restrict__ Bw,
                     float* __restrict__ part) {
    extern __shared__ float dsm[];

    const int tid = threadIdx.x;
    const int tc  = tid & 31;
    const int tr  = tid >> 5;
    const uint32_t sbase = smem_u32(dsm);

    const int ar = tid >> 1, ah = tid & 1;

    for (int u = blockIdx.x; u < NUNITS; u += GRID1) {
        const int tile = u & 127;
        const int kq   = u >> 7;
        const int m0   = tile * 128;
        const size_t koff = (size_t)kq * (UCHUNK * G1_BK);

        ull acc[8][8];
        #pragma unroll
        for (int p = 0; p < 8; p++)
            #pragma unroll
            for (int j = 0; j < 8; j++) acc[p][j] = 0ull;

        const float* aptr = A + (size_t)(m0 + ar) * D_ + koff + ah * 8;
        const float* bptr = Bw + (size_t)tid * D_ + koff;

        float4 areg[2], breg[4];

        areg[0] = *(const float4*)(aptr + 0);
        areg[1] = *(const float4*)(aptr + 4);
        breg[0] = *(const float4*)(bptr + 0);
        breg[1] = *(const float4*)(bptr + 4);
        breg[2] = *(const float4*)(bptr + 8);
        breg[3] = *(const float4*)(bptr + 12);
        {
            float* As = dsm;
            float* Bs = dsm + G1_BK * 128;
            const float av[8] = {areg[0].x, areg[0].y, areg[0].z, areg[0].w,
                                 areg[1].x, areg[1].y, areg[1].z, areg[1].w};
            #pragma unroll
            for (int i = 0; i < 8; i++) As[(ah * 8 + i) * 128 + ar] = av[i];
            const float bv[16] = {breg[0].x, breg[0].y, breg[0].z, breg[0].w,
                                  breg[1].x, breg[1].y, breg[1].z, breg[1].w,
                                  breg[2].x, breg[2].y, breg[2].z, breg[2].w,
                                  breg[3].x, breg[3].y, breg[3].z, breg[3].w};
            #pragma unroll
            for (int i = 0; i < 16; i++) Bs[i * 256 + tid] = bv[i];
        }
        __syncthreads();

        for (int c = 0; c < UCHUNK; c++) {
            const int s = c & 1;

            if (c + 1 < UCHUNK) {
                const float* ap = aptr + (size_t)(c + 1) * G1_BK;
                const float* bp = bptr + (size_t)(c + 1) * G1_BK;
                areg[0] = *(const float4*)(ap + 0);
                areg[1] = *(const float4*)(ap + 4);
                breg[0] = *(const float4*)(bp + 0);
                breg[1] = *(const float4*)(bp + 4);
                breg[2] = *(const float4*)(bp + 8);
                breg[3] = *(const float4*)(bp + 12);
            }

            {
                const uint32_t sA = sbase + s * G1_STAGE_BYTES + tr * 64;
                const float*  Bs = dsm + s * G1_STAGE_FLOATS + G1_BK * 128 + tc * 8;
                #pragma unroll 4
                for (int k = 0; k < G1_BK; k++) {
                    ull a[8];
                    const uint32_t ab = sA + k * 512;
                    asm("ld.shared.v2.b64 {%0,%1}, [%2];"
                        : "=l"(a[0]), "=l"(a[1]) : "r"(ab));
                    asm("ld.shared.v2.b64 {%0,%1}, [%2];"
                        : "=l"(a[2]), "=l"(a[3]) : "r"(ab + 16));
                    asm("ld.shared.v2.b64 {%0,%1}, [%2];"
                        : "=l"(a[4]), "=l"(a[5]) : "r"(ab + 32));
                    asm("ld.shared.v2.b64 {%0,%1}, [%2];"
                        : "=l"(a[6]), "=l"(a[7]) : "r"(ab + 48));
                    const float4 b0 = *(const float4*)(Bs + k * 256);
                    const float4 b1 = *(const float4*)(Bs + k * 256 + 4);
                    ull bd[8];
                    bd[0] = dupf(b0.x); bd[1] = dupf(b0.y);
                    bd[2] = dupf(b0.z); bd[3] = dupf(b0.w);
                    bd[4] = dupf(b1.x); bd[5] = dupf(b1.y);
                    bd[6] = dupf(b1.z); bd[7] = dupf(b1.w);
                    #pragma unroll
                    for (int p = 0; p < 8; p++)
                        #pragma unroll
                        for (int j = 0; j < 8; j++)
                            acc[p][j] = ffma2(a[p], bd[j], acc[p][j]);
                }
            }

            if (c + 1 < UCHUNK) {
                float* As = dsm + (s ^ 1) * G1_STAGE_FLOATS;
                float* Bs = As + G1_BK * 128;
                const float av[8] = {areg[0].x, areg[0].y, areg[0].z, areg[0].w,
                                     areg[1].x, areg[1].y, areg[1].z, areg[1].w};
                #pragma unroll
                for (int i = 0; i < 8; i++) As[(ah * 8 + i) * 128 + ar] = av[i];
                const float bv[16] = {breg[0].x, breg[0].y, breg[0].z, breg[0].w,
                                      breg[1].x, breg[1].y, breg[1].z, breg[1].w,
                                      breg[2].x, breg[2].y, breg[2].z, breg[2].w,
                                      breg[3].x, breg[3].y, breg[3].z, breg[3].w};
                #pragma unroll
                for (int i = 0; i < 16; i++) Bs[i * 256 + tid] = bv[i];
            }
            __syncthreads();
        }

        float* Cp = part + (size_t)kq * (BT_ * R_);
        const int n0 = tc * 8;
        #pragma unroll
        for (int p = 0; p < 8; p++) {
            const int r0 = m0 + tr * 16 + 2 * p;
            float4 lo0 = make_float4(f2lo(acc[p][0]), f2lo(acc[p][1]),
                                     f2lo(acc[p][2]), f2lo(acc[p][3]));
            float4 lo1 = make_float4(f2lo(acc[p][4]), f2lo(acc[p][5]),
                                     f2lo(acc[p][6]), f2lo(acc[p][7]));
            float4 hi0 = make_float4(f2hi(acc[p][0]), f2hi(acc[p][1]),
                                     f2hi(acc[p][2]), f2hi(acc[p][3]));
            float4 hi1 = make_float4(f2hi(acc[p][4]), f2hi(acc[p][5]),
                                     f2hi(acc[p][6]), f2hi(acc[p][7]));
            *(float4*)(Cp + (size_t)r0 * R_ + n0)           = lo0;
            *(float4*)(Cp + (size_t)r0 * R_ + n0 + 4)       = lo1;
            *(float4*)(Cp + (size_t)(r0 + 1) * R_ + n0)     = hi0;
            *(float4*)(Cp + (size_t)(r0 + 1) * R_ + n0 + 4) = hi1;
        }
    }
}

// ---------------------------------------------------------------------------
// Reduce 8 split-K partials + bias -> xr. float4-vectorized.
// ---------------------------------------------------------------------------
__global__ __launch_bounds__(256)
void reduce8_kernel(const float* __restrict__ part,
                    const float* __restrict__ bias,
                    float* __restrict__ xr) {
    const int i = blockIdx.x * 256 + threadIdx.x;
    const size_t Q = (size_t)BT_ * R_ / 4;
    const float4* p4 = (const float4*)part;
    float4 s = p4[i];
    #pragma unroll
    for (int q = 1; q < KQ_; q++) {
        float4 v = p4[q * Q + i];
        s.x += v.x; s.y += v.y; s.z += v.z; s.w += v.w;
    }
    const int col4 = i & 63;
    const float4 b = *(const float4*)(bias + col4 * 4);
    s.x += b.x; s.y += b.y; s.z += b.z; s.w += b.w;
    ((float4*)xr)[i] = s;
}

// ---------------------------------------------------------------------------
// GEMM2 (f32x2): xp[BT,216] = xr[BT,256] @ w_ih[216,256]^T + b_ih
// ---------------------------------------------------------------------------
__global__ __launch_bounds__(256, 1)
void gemm2_f2_kernel(const float* __restrict__ A,
                     const float* __restrict__ Bw,
                     const float* __restrict__ bias,
                     float* __restrict__ C) {
    extern __shared__ float dsm[];

    const int tid = threadIdx.x;
    const int tc  = tid & 31;
    const int tr  = tid >> 5;
    const int m0  = blockIdx.x * 128;
    const uint32_t sbase = smem_u32(dsm);

    ull acc[8][8];
    #pragma unroll
    for (int p = 0; p < 8; p++)
        #pragma unroll
        for (int j = 0; j < 8; j++) acc[p][j] = 0ull;

    const int ar = tid >> 1, ah = tid & 1;
    const float* aptr = A + (size_t)(m0 + ar) * R_ + ah * 8;
    const bool bval = tid < TH3;
    const float* bptr = Bw + (size_t)(bval ? tid : 0) * R_;

    float4 areg[2], breg[4];
    const float4 z4 = make_float4(0.f, 0.f, 0.f, 0.f);

    areg[0] = *(const float4*)(aptr + 0);
    areg[1] = *(const float4*)(aptr + 4);
    breg[0] = bval ? *(const float4*)(bptr + 0)  : z4;
    breg[1] = bval ? *(const float4*)(bptr + 4)  : z4;
    breg[2] = bval ? *(const float4*)(bptr + 8)  : z4;
    breg[3] = bval ? *(const float4*)(bptr + 12) : z4;
    {
        float* As = dsm;
        float* Bs = dsm + G1_BK * 128;
        const float av[8] = {areg[0].x, areg[0].y, areg[0].z, areg[0].w,
                             areg[1].x, areg[1].y, areg[1].z, areg[1].w};
        #pragma unroll
        for (int i = 0; i < 8; i++) As[(ah * 8 + i) * 128 + ar] = av[i];
        const float bv[16] = {breg[0].x, breg[0].y, breg[0].z, breg[0].w,
                              breg[1].x, breg[1].y, breg[1].z, breg[1].w,
                              breg[2].x, breg[2].y, breg[2].z, breg[2].w,
                              breg[3].x, breg[3].y, breg[3].z, breg[3].w};
        #pragma unroll
        for (int i = 0; i < 16; i++) Bs[i * 256 + tid] = bv[i];
    }
    __syncthreads();

    for (int c = 0; c < G2_NCH; c++) {
        const int s = c & 1;

        if (c + 1 < G2_NCH) {
            const float* ap = aptr + (size_t)(c + 1) * G1_BK;
            const float* bp = bptr + (size_t)(c + 1) * G1_BK;
            areg[0] = *(const float4*)(ap + 0);
            areg[1] = *(const float4*)(ap + 4);
            breg[0] = bval ? *(const float4*)(bp + 0)  : z4;
            breg[1] = bval ? *(const float4*)(bp + 4)  : z4;
            breg[2] = bval ? *(const float4*)(bp + 8)  : z4;
            breg[3] = bval ? *(const float4*)(bp + 12) : z4;
        }

        {
            const uint32_t sA = sbase + s * G1_STAGE_BYTES + tr * 64;
            const float*  Bs = dsm + s * G1_STAGE_FLOATS + G1_BK * 128 + tc * 8;
            #pragma unroll 4
            for (int k = 0; k < G1_BK; k++) {
                ull a[8];
                const uint32_t ab = sA + k * 512;
                asm("ld.shared.v2.b64 {%0,%1}, [%2];"
                    : "=l"(a[0]), "=l"(a[1]) : "r"(ab));
                asm("ld.shared.v2.b64 {%0,%1}, [%2];"
                    : "=l"(a[2]), "=l"(a[3]) : "r"(ab + 16));
                asm("ld.shared.v2.b64 {%0,%1}, [%2];"
                    : "=l"(a[4]), "=l"(a[5]) : "r"(ab + 32));
                asm("ld.shared.v2.b64 {%0,%1}, [%2];"
                    : "=l"(a[6]), "=l"(a[7]) : "r"(ab + 48));
                const float4 b0 = *(const float4*)(Bs + k * 256);
                const float4 b1 = *(const float4*)(Bs + k * 256 + 4);
                ull bd[8];
                bd[0] = dupf(b0.x); bd[1] = dupf(b0.y);
                bd[2] = dupf(b0.z); bd[3] = dupf(b0.w);
                bd[4] = dupf(b1.x); bd[5] = dupf(b1.y);
                bd[6] = dupf(b1.z); bd[7] = dupf(b1.w);
                #pragma unroll
                for (int p = 0; p < 8; p++)
                    #pragma unroll
                    for (int j = 0; j < 8; j++)
                        acc[p][j] = ffma2(a[p], bd[j], acc[p][j]);
            }
        }

        if (c + 1 < G2_NCH) {
            float* As = dsm + (s ^ 1) * G1_STAGE_FLOATS;
            float* Bs = As + G1_BK * 128;
            const float av[8] = {areg[0].x, areg[0].y, areg[0].z, areg[0].w,
                                 areg[1].x, areg[1].y, areg[1].z, areg[1].w};
            #pragma unroll
            for (int i = 0; i < 8; i++) As[(ah * 8 + i) * 128 + ar] = av[i];
            const float bv[16] = {breg[0].x, breg[0].y, breg[0].z, breg[0].w,
                                  breg[1].x, breg[1].y, breg[1].z, breg[1].w,
                                  breg[2].x, breg[2].y, breg[2].z, breg[2].w,
                                  breg[3].x, breg[3].y, breg[3].z, breg[3].w};
            #pragma unroll
            for (int i = 0; i < 16; i++) Bs[i * 256 + tid] = bv[i];
        }
        __syncthreads();
    }

    if (tc < 27) {
        const int n0 = tc * 8;
        const float4 bia0 = *(const float4*)(bias + n0);
        const float4 bia1 = *(const float4*)(bias + n0 + 4);
        #pragma unroll
        for (int p = 0; p < 8; p++) {
            const int r0 = m0 + tr * 16 + 2 * p;
            float4 lo0 = make_float4(f2lo(acc[p][0]) + bia0.x, f2lo(acc[p][1]) + bia0.y,
                                     f2lo(acc[p][2]) + bia0.z, f2lo(acc[p][3]) + bia0.w);
            float4 lo1 = make_float4(f2lo(acc[p][4]) + bia1.x, f2lo(acc[p][5]) + bia1.y,
                                     f2lo(acc[p][6]) + bia1.z, f2lo(acc[p][7]) + bia1.w);
            float4 hi0 = make_float4(f2hi(acc[p][0]) + bia0.x, f2hi(acc[p][1]) + bia0.y,
                                     f2hi(acc[p][2]) + bia0.z, f2hi(acc[p][3]) + bia0.w);
            float4 hi1 = make_float4(f2hi(acc[p][4]) + bia1.x, f2hi(acc[p][5]) + bia1.y,
                                     f2hi(acc[p][6]) + bia1.z, f2hi(acc[p][7]) + bia1.w);
            *(float4*)(C + (size_t)r0 * TH3 + n0)           = lo0;
            *(float4*)(C + (size_t)r0 * TH3 + n0 + 4)       = lo1;
            *(float4*)(C + (size_t)(r0 + 1) * TH3 + n0)     = hi0;
            *(float4*)(C + (size_t)(r0 + 1) * TH3 + n0 + 4) = hi1;
        }
    }
}

// ---------------------------------------------------------------------------
// GRU: one block per batch element. q-reduction removed from the loop —
// h_t streamed to gmem (hseq); q computed by qgemv_kernel afterwards.
// 4-way split accumulator chains; xp prefetched 2 steps ahead.
// ---------------------------------------------------------------------------
__global__ __launch_bounds__(224, 1)
void gru_kernel(const float* __restrict__ xp,
                const float* __restrict__ w_hh,
                const float* __restrict__ b_hh,
                float* __restrict__ hseq)
{
    const int b = blockIdx.x;
    const int j = threadIdx.x;

    __shared__ __align__(16) float h[H_];
    __shared__ float hp[TH3];
    __shared__ float xv[TH3];

    ull w2[36];
    ull bh2 = 0ull;
    if (j < TH3) {
        #pragma unroll
        for (int i = 0; i < 36; i++)
            w2[i] = packf(w_hh[j * H_ + 2 * i], w_hh[j * H_ + 2 * i + 1]);
        bh2 = packf(b_hh[j], 0.f);
    }
    if (j < H_) h[j] = 0.f;

    const uint32_t hb = smem_u32(h);
    const float* xprow = xp + (size_t)b * T_ * TH3;
    float* hrow = hseq + (size_t)b * T_ * H_;

    float xpv0 = (j < TH3) ? xprow[j] : 0.f;
    float xpv1 = (j < TH3 && T_ > 1) ? xprow[TH3 + j] : 0.f;
    __syncthreads();

    for (int t = 0; t < T_; t++) {
        if (j < TH3) {
            ull a0 = bh2, a1 = 0ull, a2 = 0ull, a3 = 0ull;
            #pragma unroll
            for (int i = 0; i < 9; i++) {
                ull p0, p1;
                asm volatile("ld.shared.v2.b64 {%0,%1}, [%2];"
                             : "=l"(p0), "=l"(p1) : "r"(hb + i * 16));
                if (i & 1) {
                    a2 = ffma2(w2[2 * i],     p0, a2);
                    a3 = ffma2(w2[2 * i + 1], p1, a3);
                } else {
                    a0 = ffma2(w2[2 * i],     p0, a0);
                    a1 = ffma2(w2[2 * i + 1], p1, a1);
                }
            }
            ull s = fadd2(fadd2(a0, a2), fadd2(a1, a3));
            hp[j] = f2lo(s) + f2hi(s);
            xv[j] = xpv0;
        }
        // prefetch xp for t+2 (two-step window covers L2 latency)
        float xnext = 0.f;
        if (j < TH3 && t + 2 < T_) xnext = xprow[(size_t)(t + 2) * TH3 + j];
        __syncthreads();

        if (j < H_) {
            float r  = __fdividef(1.f, 1.f + __expf(-(xv[j]        + hp[j])));
            float z  = __fdividef(1.f, 1.f + __expf(-(xv[j + H_]   + hp[j + H_])));
            float n  = tanh_fast(xv[j + 2 * H_] + r * hp[j + 2 * H_]);
            float hn = (1.f - z) * n + z * h[j];
            h[j] = hn;
            hrow[(size_t)t * H_ + j] = hn;   // fire-and-forget
        }
        __syncthreads();

        xpv0 = xpv1;
        xpv1 = xnext;
    }
}

// ---------------------------------------------------------------------------
// q[b,t] = dot(hseq[b,t,:], w_reg) + b_reg.  128 rows per block, smem-staged
// with pad-73 layout (conflict-free LDS).
// ---------------------------------------------------------------------------
__global__ __launch_bounds__(128)
void qgemv_kernel(const float* __restrict__ hseq,
                  const float* __restrict__ w_reg,
                  const float* __restrict__ b_reg,
                  float* __restrict__ q)
{
    __shared__ float sh[128 * 73];
    __shared__ float swr[H_];

    const int tid  = threadIdx.x;
    const int row0 = blockIdx.x * 128;

    // stage 128 rows (128*72 floats) coalesced as float4 (72 % 4 == 0)
    const float4* src = (const float4*)(hseq + (size_t)row0 * H_);
    for (int i = tid; i < 128 * (H_ / 4); i += 128) {
        const int r  = i / (H_ / 4);
        const int c4 = i - r * (H_ / 4);
        float4 v = src[i];
        float* d = &sh[r * 73 + c4 * 4];
        d[0] = v.x; d[1] = v.y; d[2] = v.z; d[3] = v.w;
    }
    if (tid < H_) swr[tid] = w_reg[tid];
    __syncthreads();

    float acc = b_reg[0];
    const float* hr = &sh[tid * 73];
    #pragma unroll
    for (int i = 0; i < H_; i++) acc = fmaf(hr[i], swr[i], acc);
    q[row0 + tid] = acc;
}

// ---------------------------------------------------------------------------
// sitp + sigmoid heads
// ---------------------------------------------------------------------------
__global__ __launch_bounds__(1024, 1)
void sitp_kernel(const float* __restrict__ q,
                 const int*   __restrict__ xlen,
                 const float* __restrict__ nlm_w1, const float* __restrict__ nlm_b1,
                 const float* __restrict__ nlm_w2, const float* __restrict__ nlm_b2,
                 const float* __restrict__ lm_w,   const float* __restrict__ lm_b,
                 float* __restrict__ out)
{
    const int b = blockIdx.x;
    const int t = threadIdx.x;

    __shared__ float qs[T_];
    __shared__ float ws[T_];
    __shared__ float wqs[T_];
    __shared__ float warpsum[32];

    const int len = xlen[b];
    const float qv = q[b * T_ + t];
    const bool valid = t < len;

    qs[t] = qv;
    const float wv = valid ? expf(-qv) : 0.f;
    ws[t]  = wv;
    wqs[t] = wv * qv;
    __syncthreads();

    float c = 0.f;
    if (valid) {
        float xmin = qv;
        #pragma unroll
        for (int d = 1; d < TAU; d++) {
            int s = t - d;
            if (s >= 0) xmin = fminf(xmin, qs[s]);
        }
        float num = 0.f, den = 0.f;
        #pragma unroll
        for (int d = 0; d < TAU; d++) {
            int s = t + d;
            if (s < T_) { num += wqs[s]; den += ws[s]; }
        }
        float y = (den > 0.f) ? num / fmaxf(den, 1e-30f) : 0.f;
        c = 0.5f * y + 0.5f * xmin;
    }

    #pragma unroll
    for (int off = 16; off > 0; off >>= 1)
        c += __shfl_down_sync(0xFFFFFFFFu, c, off);
    const int wid  = t >> 5;
    const int lane = t & 31;
    if (lane == 0) warpsum[wid] = c;
    __syncthreads();
    if (wid == 0) {
        float v = warpsum[lane];
        #pragma unroll
        for (int off = 16; off > 0; off >>= 1)
            v += __shfl_down_sync(0xFFFFFFFFu, v, off);
        if (lane == 0) {
            const float s        = v / (float)len;
            const float relative = 1.f / (1.f + expf(-s));
            const float mapped   = (1.f / (1.f + expf(-(nlm_w1[0] * relative + nlm_b1[0]))))
                                   * nlm_w2[0] + nlm_b2[0];
            const float aligned  = lm_w[0] * mapped + lm_b[0];
            out[b]          = relative;
            out[B_ + b]     = mapped;
            out[2 * B_ + b] = aligned;
        }
    }
}

// ---------------------------------------------------------------------------
// Launch
// ---------------------------------------------------------------------------
extern "C" void kernel_launch(void* const* d_in, const int* in_sizes, int n_in,
                              void* d_out, int out_size)
{
    const float* x     = (const float*)d_in[0];
    const int*   x_len = (const int*)  d_in[1];
    const float* w_dr  = (const float*)d_in[2];
    const float* b_dr  = (const float*)d_in[3];
    const float* w_ih  = (const float*)d_in[4];
    const float* w_hh  = (const float*)d_in[5];
    const float* b_ih  = (const float*)d_in[6];
    const float* b_hh  = (const float*)d_in[7];
    const float* w_reg = (const float*)d_in[8];
    const float* b_reg = (const float*)d_in[9];
    const float* nlm_w1 = (const float*)d_in[10];
    const float* nlm_b1 = (const float*)d_in[11];
    const float* nlm_w2 = (const float*)d_in[12];
    const float* nlm_b2 = (const float*)d_in[13];
    const float* lm_w   = (const float*)d_in[14];
    const float* lm_b   = (const float*)d_in[15];
    float* out = (float*)d_out;

    float* part; cudaGetSymbolAddress((void**)&part, g_part);
    float* xr;   cudaGetSymbolAddress((void**)&xr,   g_xr);
    float* xpp;  cudaGetSymbolAddress((void**)&xpp,  g_xp);
    float* hs;   cudaGetSymbolAddress((void**)&hs,   g_hseq);
    float* qq;   cudaGetSymbolAddress((void**)&qq,   g_q);

    static bool attr_done = false;
    if (!attr_done) {
        cudaFuncSetAttribute(gemm1_f2_kernel,
                             cudaFuncAttributeMaxDynamicSharedMemorySize, G1_DYN);
        cudaFuncSetAttribute(gemm2_f2_kernel,
                             cudaFuncAttributeMaxDynamicSharedMemorySize, G1_DYN);
        attr_done = true;
    }

    // Stage A: split-K persistent GEMM1 -> 8 partial slabs
    gemm1_f2_kernel<<<GRID1, 256, G1_DYN>>>(x, w_dr, part);
    // Stage A2: reduce partials + bias -> xr
    reduce8_kernel<<<(BT_ * R_ / 4) / 256, 256>>>(part, b_dr, xr);
    // Stage B: xp = xr @ w_ih^T + b_ih  (f32x2)
    gemm2_f2_kernel<<<BT_ / 128, 256, G1_DYN>>>(xr, w_ih, b_ih, xpp);
    // Stage C: GRU recurrence -> hseq
    gru_kernel<<<B_, 224>>>(xpp, w_hh, b_hh, hs);
    // Stage C2: q = hseq @ w_reg + b_reg
    qgemv_kernel<<<BT_ / 128, 128>>>(hs, w_reg, b_reg, qq);
    // Stage D: sitp windows + heads
    sitp_kernel<<<B_, T_>>>(qq, x_len, nlm_w1, nlm_b1, nlm_w2, nlm_b2,
                            lm_w, lm_b, out);
}

// round 12
// speedup vs baseline: 1.5355x; 1.5355x over previous
#include <cuda_runtime.h>
#include <cuda_bf16.h>
#include <math.h>
#include <stdint.h>

typedef unsigned long long ull;

// ---------------------------------------------------------------------------
// Problem dims (fixed by the dataset)
// ---------------------------------------------------------------------------
#define B_  16
#define T_  1024
#define D_  8704
#define R_  256
#define H_  72
#define TH3 (3 * H_)   // 216
#define TAU 12
#define BT_ (B_ * T_)

// GEMM1 tiling / unit schedule
#define G1_BK   16
#define KQ_     8                       // k-split factor
#define UCHUNK  (D_ / G1_BK / KQ_)      // 68 chunks per unit
#define NUNITS  (128 * KQ_)             // 1024
#define GRID1   148                     // persistent CTAs (1/SM)
#define G1_STAGE_FLOATS (G1_BK * 128 + G1_BK * 256)   // 6144
#define G1_STAGE_BYTES  (G1_STAGE_FLOATS * 4)         // 24576
#define G1_DYN  (2 * G1_STAGE_BYTES)                  // 49152 = 48KB

// GEMM2
#define G2_NCH  (R_ / G1_BK)            // 16

// ---------------------------------------------------------------------------
// Scratch (no cudaMalloc allowed -> __device__ globals)
// ---------------------------------------------------------------------------
__device__ float g_part[KQ_][BT_ * R_];     // 134MB split-K partials
__device__ float g_xr[BT_ * R_];            // [B*T, R]
__device__ float g_xp[BT_ * TH3];           // [B*T, 3H]
__device__ float g_hseq[BT_ * H_];          // [B*T, H] GRU hidden history
__device__ float g_q [BT_];                 // [B, T]

// ---------------------------------------------------------------------------
// f32x2 packed helpers
// ---------------------------------------------------------------------------
__device__ __forceinline__ uint32_t smem_u32(const void* p) {
    uint32_t a;
    asm("{ .reg .u64 t; cvta.to.shared.u64 t, %1; cvt.u32.u64 %0, t; }"
        : "=r"(a) : "l"(p));
    return a;
}

__device__ __forceinline__ ull ffma2(ull a, ull b, ull c) {
    ull d;
    asm("fma.rn.f32x2 %0, %1, %2, %3;" : "=l"(d) : "l"(a), "l"(b), "l"(c));
    return d;
}

__device__ __forceinline__ ull fadd2(ull a, ull b) {
    ull d;
    asm("add.rn.f32x2 %0, %1, %2;" : "=l"(d) : "l"(a), "l"(b));
    return d;
}

__device__ __forceinline__ ull dupf(float f) {
    ull d;
    asm("mov.b64 %0, {%1, %1};" : "=l"(d) : "r"(__float_as_uint(f)));
    return d;
}

__device__ __forceinline__ ull packf(float lo, float hi) {
    ull d;
    asm("mov.b64 %0, {%1, %2};" : "=l"(d)
        : "r"(__float_as_uint(lo)), "r"(__float_as_uint(hi)));
    return d;
}

__device__ __forceinline__ float f2lo(ull u) {
    return __uint_as_float((uint32_t)u);
}
__device__ __forceinline__ float f2hi(ull u) {
    return __uint_as_float((uint32_t)(u >> 32));
}

__device__ __forceinline__ float tanh_fast(float x) {
    float y;
    asm("tanh.approx.f32 %0, %1;" : "=f"(y) : "f"(x));
    return y;
}

// ---------------------------------------------------------------------------
// GEMM1 (split-K persistent): part[kq][m,n] = x[m, kq-slice] @ w_dr^T
// ---------------------------------------------------------------------------
__global__ __launch_bounds__(256, 1)
void gemm1_f2_kernel(const float* __restrict__ A,
                     const float* __restrict__ Bw,
                     float* __restrict__ part) {
    extern __shared__ float dsm[];

    const int tid = threadIdx.x;
    const int tc  = tid & 31;
    const int tr  = tid >> 5;
    const uint32_t sbase = smem_u32(dsm);

    const int ar = tid >> 1, ah = tid & 1;

    for (int u = blockIdx.x; u < NUNITS; u += GRID1) {
        const int tile = u & 127;
        const int kq   = u >> 7;
        const int m0   = tile * 128;
        const size_t koff = (size_t)kq * (UCHUNK * G1_BK);

        ull acc[8][8];
        #pragma unroll
        for (int p = 0; p < 8; p++)
            #pragma unroll
            for (int j = 0; j < 8; j++) acc[p][j] = 0ull;

        const float* aptr = A + (size_t)(m0 + ar) * D_ + koff + ah * 8;
        const float* bptr = Bw + (size_t)tid * D_ + koff;

        float4 areg[2], breg[4];

        areg[0] = *(const float4*)(aptr + 0);
        areg[1] = *(const float4*)(aptr + 4);
        breg[0] = *(const float4*)(bptr + 0);
        breg[1] = *(const float4*)(bptr + 4);
        breg[2] = *(const float4*)(bptr + 8);
        breg[3] = *(const float4*)(bptr + 12);
        {
            float* As = dsm;
            float* Bs = dsm + G1_BK * 128;
            const float av[8] = {areg[0].x, areg[0].y, areg[0].z, areg[0].w,
                                 areg[1].x, areg[1].y, areg[1].z, areg[1].w};
            #pragma unroll
            for (int i = 0; i < 8; i++) As[(ah * 8 + i) * 128 + ar] = av[i];
            const float bv[16] = {breg[0].x, breg[0].y, breg[0].z, breg[0].w,
                                  breg[1].x, breg[1].y, breg[1].z, breg[1].w,
                                  breg[2].x, breg[2].y, breg[2].z, breg[2].w,
                                  breg[3].x, breg[3].y, breg[3].z, breg[3].w};
            #pragma unroll
            for (int i = 0; i < 16; i++) Bs[i * 256 + tid] = bv[i];
        }
        __syncthreads();

        for (int c = 0; c < UCHUNK; c++) {
            const int s = c & 1;

            if (c + 1 < UCHUNK) {
                const float* ap = aptr + (size_t)(c + 1) * G1_BK;
                const float* bp = bptr + (size_t)(c + 1) * G1_BK;
                areg[0] = *(const float4*)(ap + 0);
                areg[1] = *(const float4*)(ap + 4);
                breg[0] = *(const float4*)(bp + 0);
                breg[1] = *(const float4*)(bp + 4);
                breg[2] = *(const float4*)(bp + 8);
                breg[3] = *(const float4*)(bp + 12);
            }

            {
                const uint32_t sA = sbase + s * G1_STAGE_BYTES + tr * 64;
                const float*  Bs = dsm + s * G1_STAGE_FLOATS + G1_BK * 128 + tc * 8;
                #pragma unroll 4
                for (int k = 0; k < G1_BK; k++) {
                    ull a[8];
                    const uint32_t ab = sA + k * 512;
                    asm("ld.shared.v2.b64 {%0,%1}, [%2];"
                        : "=l"(a[0]), "=l"(a[1]) : "r"(ab));
                    asm("ld.shared.v2.b64 {%0,%1}, [%2];"
                        : "=l"(a[2]), "=l"(a[3]) : "r"(ab + 16));
                    asm("ld.shared.v2.b64 {%0,%1}, [%2];"
                        : "=l"(a[4]), "=l"(a[5]) : "r"(ab + 32));
                    asm("ld.shared.v2.b64 {%0,%1}, [%2];"
                        : "=l"(a[6]), "=l"(a[7]) : "r"(ab + 48));
                    const float4 b0 = *(const float4*)(Bs + k * 256);
                    const float4 b1 = *(const float4*)(Bs + k * 256 + 4);
                    ull bd[8];
                    bd[0] = dupf(b0.x); bd[1] = dupf(b0.y);
                    bd[2] = dupf(b0.z); bd[3] = dupf(b0.w);
                    bd[4] = dupf(b1.x); bd[5] = dupf(b1.y);
                    bd[6] = dupf(b1.z); bd[7] = dupf(b1.w);
                    #pragma unroll
                    for (int p = 0; p < 8; p++)
                        #pragma unroll
                        for (int j = 0; j < 8; j++)
                            acc[p][j] = ffma2(a[p], bd[j], acc[p][j]);
                }
            }

            if (c + 1 < UCHUNK) {
                float* As = dsm + (s ^ 1) * G1_STAGE_FLOATS;
                float* Bs = As + G1_BK * 128;
                const float av[8] = {areg[0].x, areg[0].y, areg[0].z, areg[0].w,
                                     areg[1].x, areg[1].y, areg[1].z, areg[1].w};
                #pragma unroll
                for (int i = 0; i < 8; i++) As[(ah * 8 + i) * 128 + ar] = av[i];
                const float bv[16] = {breg[0].x, breg[0].y, breg[0].z, breg[0].w,
                                      breg[1].x, breg[1].y, breg[1].z, breg[1].w,
                                      breg[2].x, breg[2].y, breg[2].z, breg[2].w,
                                      breg[3].x, breg[3].y, breg[3].z, breg[3].w};
                #pragma unroll
                for (int i = 0; i < 16; i++) Bs[i * 256 + tid] = bv[i];
            }
            __syncthreads();
        }

        float* Cp = part + (size_t)kq * (BT_ * R_);
        const int n0 = tc * 8;
        #pragma unroll
        for (int p = 0; p < 8; p++) {
            const int r0 = m0 + tr * 16 + 2 * p;
            float4 lo0 = make_float4(f2lo(acc[p][0]), f2lo(acc[p][1]),
                                     f2lo(acc[p][2]), f2lo(acc[p][3]));
            float4 lo1 = make_float4(f2lo(acc[p][4]), f2lo(acc[p][5]),
                                     f2lo(acc[p][6]), f2lo(acc[p][7]));
            float4 hi0 = make_float4(f2hi(acc[p][0]), f2hi(acc[p][1]),
                                     f2hi(acc[p][2]), f2hi(acc[p][3]));
            float4 hi1 = make_float4(f2hi(acc[p][4]), f2hi(acc[p][5]),
                                     f2hi(acc[p][6]), f2hi(acc[p][7]));
            *(float4*)(Cp + (size_t)r0 * R_ + n0)           = lo0;
            *(float4*)(Cp + (size_t)r0 * R_ + n0 + 4)       = lo1;
            *(float4*)(Cp + (size_t)(r0 + 1) * R_ + n0)     = hi0;
            *(float4*)(Cp + (size_t)(r0 + 1) * R_ + n0 + 4) = hi1;
        }
    }
}

// ---------------------------------------------------------------------------
// Reduce 8 split-K partials + bias -> xr. float4-vectorized.
// ---------------------------------------------------------------------------
__global__ __launch_bounds__(256)
void reduce8_kernel(const float* __restrict__ part,
                    const float* __restrict__ bias,
                    float* __restrict__ xr) {
    const int i = blockIdx.x * 256 + threadIdx.x;
    const size_t Q = (size_t)BT_ * R_ / 4;
    const float4* p4 = (const float4*)part;
    float4 s = p4[i];
    #pragma unroll
    for (int q = 1; q < KQ_; q++) {
        float4 v = p4[q * Q + i];
        s.x += v.x; s.y += v.y; s.z += v.z; s.w += v.w;
    }
    const int col4 = i & 63;
    const float4 b = *(const float4*)(bias + col4 * 4);
    s.x += b.x; s.y += b.y; s.z += b.z; s.w += b.w;
    ((float4*)xr)[i] = s;
}

// ---------------------------------------------------------------------------
// GEMM2 (f32x2): xp[BT,216] = xr[BT,256] @ w_ih[216,256]^T + b_ih
// ---------------------------------------------------------------------------
__global__ __launch_bounds__(256, 1)
void gemm2_f2_kernel(const float* __restrict__ A,
                     const float* __restrict__ Bw,
                     const float* __restrict__ bias,
                     float* __restrict__ C) {
    extern __shared__ float dsm[];

    const int tid = threadIdx.x;
    const int tc  = tid & 31;
    const int tr  = tid >> 5;
    const int m0  = blockIdx.x * 128;
    const uint32_t sbase = smem_u32(dsm);

    ull acc[8][8];
    #pragma unroll
    for (int p = 0; p < 8; p++)
        #pragma unroll
        for (int j = 0; j < 8; j++) acc[p][j] = 0ull;

    const int ar = tid >> 1, ah = tid & 1;
    const float* aptr = A + (size_t)(m0 + ar) * R_ + ah * 8;
    const bool bval = tid < TH3;
    const float* bptr = Bw + (size_t)(bval ? tid : 0) * R_;

    float4 areg[2], breg[4];
    const float4 z4 = make_float4(0.f, 0.f, 0.f, 0.f);

    areg[0] = *(const float4*)(aptr + 0);
    areg[1] = *(const float4*)(aptr + 4);
    breg[0] = bval ? *(const float4*)(bptr + 0)  : z4;
    breg[1] = bval ? *(const float4*)(bptr + 4)  : z4;
    breg[2] = bval ? *(const float4*)(bptr + 8)  : z4;
    breg[3] = bval ? *(const float4*)(bptr + 12) : z4;
    {
        float* As = dsm;
        float* Bs = dsm + G1_BK * 128;
        const float av[8] = {areg[0].x, areg[0].y, areg[0].z, areg[0].w,
                             areg[1].x, areg[1].y, areg[1].z, areg[1].w};
        #pragma unroll
        for (int i = 0; i < 8; i++) As[(ah * 8 + i) * 128 + ar] = av[i];
        const float bv[16] = {breg[0].x, breg[0].y, breg[0].z, breg[0].w,
                              breg[1].x, breg[1].y, breg[1].z, breg[1].w,
                              breg[2].x, breg[2].y, breg[2].z, breg[2].w,
                              breg[3].x, breg[3].y, breg[3].z, breg[3].w};
        #pragma unroll
        for (int i = 0; i < 16; i++) Bs[i * 256 + tid] = bv[i];
    }
    __syncthreads();

    for (int c = 0; c < G2_NCH; c++) {
        const int s = c & 1;

        if (c + 1 < G2_NCH) {
            const float* ap = aptr + (size_t)(c + 1) * G1_BK;
            const float* bp = bptr + (size_t)(c + 1) * G1_BK;
            areg[0] = *(const float4*)(ap + 0);
            areg[1] = *(const float4*)(ap + 4);
            breg[0] = bval ? *(const float4*)(bp + 0)  : z4;
            breg[1] = bval ? *(const float4*)(bp + 4)  : z4;
            breg[2] = bval ? *(const float4*)(bp + 8)  : z4;
            breg[3] = bval ? *(const float4*)(bp + 12) : z4;
        }

        {
            const uint32_t sA = sbase + s * G1_STAGE_BYTES + tr * 64;
            const float*  Bs = dsm + s * G1_STAGE_FLOATS + G1_BK * 128 + tc * 8;
            #pragma unroll 4
            for (int k = 0; k < G1_BK; k++) {
                ull a[8];
                const uint32_t ab = sA + k * 512;
                asm("ld.shared.v2.b64 {%0,%1}, [%2];"
                    : "=l"(a[0]), "=l"(a[1]) : "r"(ab));
                asm("ld.shared.v2.b64 {%0,%1}, [%2];"
                    : "=l"(a[2]), "=l"(a[3]) : "r"(ab + 16));
                asm("ld.shared.v2.b64 {%0,%1}, [%2];"
                    : "=l"(a[4]), "=l"(a[5]) : "r"(ab + 32));
                asm("ld.shared.v2.b64 {%0,%1}, [%2];"
                    : "=l"(a[6]), "=l"(a[7]) : "r"(ab + 48));
                const float4 b0 = *(const float4*)(Bs + k * 256);
                const float4 b1 = *(const float4*)(Bs + k * 256 + 4);
                ull bd[8];
                bd[0] = dupf(b0.x); bd[1] = dupf(b0.y);
                bd[2] = dupf(b0.z); bd[3] = dupf(b0.w);
                bd[4] = dupf(b1.x); bd[5] = dupf(b1.y);
                bd[6] = dupf(b1.z); bd[7] = dupf(b1.w);
                #pragma unroll
                for (int p = 0; p < 8; p++)
                    #pragma unroll
                    for (int j = 0; j < 8; j++)
                        acc[p][j] = ffma2(a[p], bd[j], acc[p][j]);
            }
        }

        if (c + 1 < G2_NCH) {
            float* As = dsm + (s ^ 1) * G1_STAGE_FLOATS;
            float* Bs = As + G1_BK * 128;
            const float av[8] = {areg[0].x, areg[0].y, areg[0].z, areg[0].w,
                                 areg[1].x, areg[1].y, areg[1].z, areg[1].w};
            #pragma unroll
            for (int i = 0; i < 8; i++) As[(ah * 8 + i) * 128 + ar] = av[i];
            const float bv[16] = {breg[0].x, breg[0].y, breg[0].z, breg[0].w,
                                  breg[1].x, breg[1].y, breg[1].z, breg[1].w,
                                  breg[2].x, breg[2].y, breg[2].z, breg[2].w,
                                  breg[3].x, breg[3].y, breg[3].z, breg[3].w};
            #pragma unroll
            for (int i = 0; i < 16; i++) Bs[i * 256 + tid] = bv[i];
        }
        __syncthreads();
    }

    if (tc < 27) {
        const int n0 = tc * 8;
        const float4 bia0 = *(const float4*)(bias + n0);
        const float4 bia1 = *(const float4*)(bias + n0 + 4);
        #pragma unroll
        for (int p = 0; p < 8; p++) {
            const int r0 = m0 + tr * 16 + 2 * p;
            float4 lo0 = make_float4(f2lo(acc[p][0]) + bia0.x, f2lo(acc[p][1]) + bia0.y,
                                     f2lo(acc[p][2]) + bia0.z, f2lo(acc[p][3]) + bia0.w);
            float4 lo1 = make_float4(f2lo(acc[p][4]) + bia1.x, f2lo(acc[p][5]) + bia1.y,
                                     f2lo(acc[p][6]) + bia1.z, f2lo(acc[p][7]) + bia1.w);
            float4 hi0 = make_float4(f2hi(acc[p][0]) + bia0.x, f2hi(acc[p][1]) + bia0.y,
                                     f2hi(acc[p][2]) + bia0.z, f2hi(acc[p][3]) + bia0.w);
            float4 hi1 = make_float4(f2hi(acc[p][4]) + bia1.x, f2hi(acc[p][5]) + bia1.y,
                                     f2hi(acc[p][6]) + bia1.z, f2hi(acc[p][7]) + bia1.w);
            *(float4*)(C + (size_t)r0 * TH3 + n0)           = lo0;
            *(float4*)(C + (size_t)r0 * TH3 + n0 + 4)       = lo1;
            *(float4*)(C + (size_t)(r0 + 1) * TH3 + n0)     = hi0;
            *(float4*)(C + (size_t)(r0 + 1) * TH3 + n0 + 4) = hi1;
        }
    }
}

// ---------------------------------------------------------------------------
// GRU: one block per batch element. h_t streamed to gmem (hseq); q computed
// by qgemv_kernel afterwards. FIXED: full-H matvec (i < 18, 72 floats),
// 4-way split accumulator chains; xp prefetched 2 steps ahead.
// ---------------------------------------------------------------------------
__global__ __launch_bounds__(224, 1)
void gru_kernel(const float* __restrict__ xp,
                const float* __restrict__ w_hh,
                const float* __restrict__ b_hh,
                float* __restrict__ hseq)
{
    const int b = blockIdx.x;
    const int j = threadIdx.x;

    __shared__ __align__(16) float h[H_];
    __shared__ float hp[TH3];
    __shared__ float xv[TH3];

    ull w2[36];
    ull bh2 = 0ull;
    if (j < TH3) {
        #pragma unroll
        for (int i = 0; i < 36; i++)
            w2[i] = packf(w_hh[j * H_ + 2 * i], w_hh[j * H_ + 2 * i + 1]);
        bh2 = packf(b_hh[j], 0.f);
    }
    if (j < H_) h[j] = 0.f;

    const uint32_t hb = smem_u32(h);
    const float* xprow = xp + (size_t)b * T_ * TH3;
    float* hrow = hseq + (size_t)b * T_ * H_;

    float xpv0 = (j < TH3) ? xprow[j] : 0.f;
    float xpv1 = (j < TH3 && T_ > 1) ? xprow[TH3 + j] : 0.f;
    __syncthreads();

    for (int t = 0; t < T_; t++) {
        if (j < TH3) {
            ull a0 = bh2, a1 = 0ull, a2 = 0ull, a3 = 0ull;
            #pragma unroll
            for (int i = 0; i < 18; i++) {           // FULL H=72 (18*4 floats)
                ull p0, p1;
                asm volatile("ld.shared.v2.b64 {%0,%1}, [%2];"
                             : "=l"(p0), "=l"(p1) : "r"(hb + i * 16));
                if (i & 1) {
                    a2 = ffma2(w2[2 * i],     p0, a2);
                    a3 = ffma2(w2[2 * i + 1], p1, a3);
                } else {
                    a0 = ffma2(w2[2 * i],     p0, a0);
                    a1 = ffma2(w2[2 * i + 1], p1, a1);
                }
            }
            ull s = fadd2(fadd2(a0, a2), fadd2(a1, a3));
            hp[j] = f2lo(s) + f2hi(s);
            xv[j] = xpv0;
        }
        // prefetch xp for t+2 (two-step window covers L2 latency)
        float xnext = 0.f;
        if (j < TH3 && t + 2 < T_) xnext = xprow[(size_t)(t + 2) * TH3 + j];
        __syncthreads();

        if (j < H_) {
            float r  = __fdividef(1.f, 1.f + __expf(-(xv[j]        + hp[j])));
            float z  = __fdividef(1.f, 1.f + __expf(-(xv[j + H_]   + hp[j + H_])));
            float n  = tanh_fast(xv[j + 2 * H_] + r * hp[j + 2 * H_]);
            float hn = (1.f - z) * n + z * h[j];
            h[j] = hn;
            hrow[(size_t)t * H_ + j] = hn;   // fire-and-forget
        }
        __syncthreads();

        xpv0 = xpv1;
        xpv1 = xnext;
    }
}

// ---------------------------------------------------------------------------
// q[b,t] = dot(hseq[b,t,:], w_reg) + b_reg.  128 rows per block, smem-staged
// with pad-73 layout (conflict-free LDS).
// ---------------------------------------------------------------------------
__global__ __launch_bounds__(128)
void qgemv_kernel(const float* __restrict__ hseq,
                  const float* __restrict__ w_reg,
                  const float* __restrict__ b_reg,
                  float* __restrict__ q)
{
    __shared__ float sh[128 * 73];
    __shared__ float swr[H_];

    const int tid  = threadIdx.x;
    const int row0 = blockIdx.x * 128;

    const float4* src = (const float4*)(hseq + (size_t)row0 * H_);
    for (int i = tid; i < 128 * (H_ / 4); i += 128) {
        const int r  = i / (H_ / 4);
        const int c4 = i - r * (H_ / 4);
        float4 v = src[i];
        float* d = &sh[r * 73 + c4 * 4];
        d[0] = v.x; d[1] = v.y; d[2] = v.z; d[3] = v.w;
    }
    if (tid < H_) swr[tid] = w_reg[tid];
    __syncthreads();

    float acc = b_reg[0];
    const float* hr = &sh[tid * 73];
    #pragma unroll
    for (int i = 0; i < H_; i++) acc = fmaf(hr[i], swr[i], acc);
    q[row0 + tid] = acc;
}

// ---------------------------------------------------------------------------
// sitp + sigmoid heads
// ---------------------------------------------------------------------------
__global__ __launch_bounds__(1024, 1)
void sitp_kernel(const float* __restrict__ q,
                 const int*   __restrict__ xlen,
                 const float* __restrict__ nlm_w1, const float* __restrict__ nlm_b1,
                 const float* __restrict__ nlm_w2, const float* __restrict__ nlm_b2,
                 const float* __restrict__ lm_w,   const float* __restrict__ lm_b,
                 float* __restrict__ out)
{
    const int b = blockIdx.x;
    const int t = threadIdx.x;

    __shared__ float qs[T_];
    __shared__ float ws[T_];
    __shared__ float wqs[T_];
    __shared__ float warpsum[32];

    const int len = xlen[b];
    const float qv = q[b * T_ + t];
    const bool valid = t < len;

    qs[t] = qv;
    const float wv = valid ? expf(-qv) : 0.f;
    ws[t]  = wv;
    wqs[t] = wv * qv;
    __syncthreads();

    float c = 0.f;
    if (valid) {
        float xmin = qv;
        #pragma unroll
        for (int d = 1; d < TAU; d++) {
            int s = t - d;
            if (s >= 0) xmin = fminf(xmin, qs[s]);
        }
        float num = 0.f, den = 0.f;
        #pragma unroll
        for (int d = 0; d < TAU; d++) {
            int s = t + d;
            if (s < T_) { num += wqs[s]; den += ws[s]; }
        }
        float y = (den > 0.f) ? num / fmaxf(den, 1e-30f) : 0.f;
        c = 0.5f * y + 0.5f * xmin;
    }

    #pragma unroll
    for (int off = 16; off > 0; off >>= 1)
        c += __shfl_down_sync(0xFFFFFFFFu, c, off);
    const int wid  = t >> 5;
    const int lane = t & 31;
    if (lane == 0) warpsum[wid] = c;
    __syncthreads();
    if (wid == 0) {
        float v = warpsum[lane];
        #pragma unroll
        for (int off = 16; off > 0; off >>= 1)
            v += __shfl_down_sync(0xFFFFFFFFu, v, off);
        if (lane == 0) {
            const float s        = v / (float)len;
            const float relative = 1.f / (1.f + expf(-s));
            const float mapped   = (1.f / (1.f + expf(-(nlm_w1[0] * relative + nlm_b1[0]))))
                                   * nlm_w2[0] + nlm_b2[0];
            const float aligned  = lm_w[0] * mapped + lm_b[0];
            out[b]          = relative;
            out[B_ + b]     = mapped;
            out[2 * B_ + b] = aligned;
        }
    }
}

// ---------------------------------------------------------------------------
// Launch
// ---------------------------------------------------------------------------
extern "C" void kernel_launch(void* const* d_in, const int* in_sizes, int n_in,
                              void* d_out, int out_size)
{
    const float* x     = (const float*)d_in[0];
    const int*   x_len = (const int*)  d_in[1];
    const float* w_dr  = (const float*)d_in[2];
    const float* b_dr  = (const float*)d_in[3];
    const float* w_ih  = (const float*)d_in[4];
    const float* w_hh  = (const float*)d_in[5];
    const float* b_ih  = (const float*)d_in[6];
    const float* b_hh  = (const float*)d_in[7];
    const float* w_reg = (const float*)d_in[8];
    const float* b_reg = (const float*)d_in[9];
    const float* nlm_w1 = (const float*)d_in[10];
    const float* nlm_b1 = (const float*)d_in[11];
    const float* nlm_w2 = (const float*)d_in[12];
    const float* nlm_b2 = (const float*)d_in[13];
    const float* lm_w   = (const float*)d_in[14];
    const float* lm_b   = (const float*)d_in[15];
    float* out = (float*)d_out;

    float* part; cudaGetSymbolAddress((void**)&part, g_part);
    float* xr;   cudaGetSymbolAddress((void**)&xr,   g_xr);
    float* xpp;  cudaGetSymbolAddress((void**)&xpp,  g_xp);
    float* hs;   cudaGetSymbolAddress((void**)&hs,   g_hseq);
    float* qq;   cudaGetSymbolAddress((void**)&qq,   g_q);

    static bool attr_done = false;
    if (!attr_done) {
        cudaFuncSetAttribute(gemm1_f2_kernel,
                             cudaFuncAttributeMaxDynamicSharedMemorySize, G1_DYN);
        cudaFuncSetAttribute(gemm2_f2_kernel,
                             cudaFuncAttributeMaxDynamicSharedMemorySize, G1_DYN);
        attr_done = true;
    }

    // Stage A: split-K persistent GEMM1 -> 8 partial slabs
    gemm1_f2_kernel<<<GRID1, 256, G1_DYN>>>(x, w_dr, part);
    // Stage A2: reduce partials + bias -> xr
    reduce8_kernel<<<(BT_ * R_ / 4) / 256, 256>>>(part, b_dr, xr);
    // Stage B: xp = xr @ w_ih^T + b_ih  (f32x2)
    gemm2_f2_kernel<<<BT_ / 128, 256, G1_DYN>>>(xr, w_ih, b_ih, xpp);
    // Stage C: GRU recurrence -> hseq
    gru_kernel<<<B_, 224>>>(xpp, w_hh, b_hh, hs);
    // Stage C2: q = hseq @ w_reg + b_reg
    qgemv_kernel<<<BT_ / 128, 128>>>(hs, w_reg, b_reg, qq);
    // Stage D: sitp windows + heads
    sitp_kernel<<<B_, T_>>>(qq, x_len, nlm_w1, nlm_b1, nlm_w2, nlm_b2,
                            lm_w, lm_b, out);
}

// round 13
// speedup vs baseline: 1.5731x; 1.0245x over previous
#include <cuda_runtime.h>
#include <cuda_bf16.h>
#include <math.h>
#include <stdint.h>

typedef unsigned long long ull;

// ---------------------------------------------------------------------------
// Problem dims
// ---------------------------------------------------------------------------
#define B_  16
#define T_  1024
#define D_  8704
#define R_  256
#define H_  72
#define TH3 (3 * H_)   // 216
#define TAU 12
#define BT_ (B_ * T_)

// GEMM1 tiling / unit schedule
#define G1_BK   16
#define KQ_     8                       // k-split factor
#define UCHUNK  (D_ / G1_BK / KQ_)      // 68 chunks per unit
#define NUNITS  (128 * KQ_)             // 1024
#define NTILES  128
#define GRID_MEGA 148                   // 16 GRU + 132 producer CTAs
#define G1_STAGE_FLOATS (G1_BK * 128 + G1_BK * 256)   // 6144
#define G1_STAGE_BYTES  (G1_STAGE_FLOATS * 4)         // 24576
#define G1_DYN  (2 * G1_STAGE_BYTES)                  // 49152

// ---------------------------------------------------------------------------
// Scratch
// ---------------------------------------------------------------------------
__device__ float g_part[KQ_][BT_ * R_];     // split-K partials
__device__ float g_xp[BT_ * TH3];           // [B*T, 3H]
__device__ float g_hseq[BT_ * H_];          // [B*T, H]
__device__ float g_q [BT_];                 // [B, T]
__device__ unsigned int g_unit_ctr;
__device__ unsigned int g_cnt [NTILES];
__device__ unsigned int g_flag[NTILES];

// ---------------------------------------------------------------------------
// helpers
// ---------------------------------------------------------------------------
__device__ __forceinline__ uint32_t smem_u32(const void* p) {
    uint32_t a;
    asm("{ .reg .u64 t; cvta.to.shared.u64 t, %1; cvt.u32.u64 %0, t; }"
        : "=r"(a) : "l"(p));
    return a;
}
__device__ __forceinline__ ull ffma2(ull a, ull b, ull c) {
    ull d; asm("fma.rn.f32x2 %0, %1, %2, %3;" : "=l"(d) : "l"(a), "l"(b), "l"(c));
    return d;
}
__device__ __forceinline__ ull fadd2(ull a, ull b) {
    ull d; asm("add.rn.f32x2 %0, %1, %2;" : "=l"(d) : "l"(a), "l"(b));
    return d;
}
__device__ __forceinline__ ull dupf(float f) {
    ull d; asm("mov.b64 %0, {%1, %1};" : "=l"(d) : "r"(__float_as_uint(f)));
    return d;
}
__device__ __forceinline__ ull packf(float lo, float hi) {
    ull d; asm("mov.b64 %0, {%1, %2};" : "=l"(d)
        : "r"(__float_as_uint(lo)), "r"(__float_as_uint(hi)));
    return d;
}
__device__ __forceinline__ float f2lo(ull u) { return __uint_as_float((uint32_t)u); }
__device__ __forceinline__ float f2hi(ull u) { return __uint_as_float((uint32_t)(u >> 32)); }
__device__ __forceinline__ float tanh_fast(float x) {
    float y; asm("tanh.approx.f32 %0, %1;" : "=f"(y) : "f"(x));
    return y;
}

// block-wide wait on a release flag (tid0 polls, then broadcast via barrier)
__device__ __forceinline__ void wait_flag(unsigned int* f) {
    if (threadIdx.x == 0) {
        while (atomicAdd(f, 0u) == 0u) { __nanosleep(200); }
        __threadfence();
    }
    __syncthreads();
}

// ---------------------------------------------------------------------------
// init: zero counters/flags (every graph replay)
// ---------------------------------------------------------------------------
__global__ void init_kernel() {
    const int t = threadIdx.x;
    if (t == 0) g_unit_ctr = 0u;
    if (t < NTILES) { g_cnt[t] = 0u; g_flag[t] = 0u; }
}

// ---------------------------------------------------------------------------
// tile finish: xr_tile = sum8(part) + b_dr (in regs), then
// xp_tile[128,216] = xr_tile @ w_ih^T + b_ih, release flag.
// Arithmetic order identical to R12's reduce8 + gemm2 (bitwise-equal output).
// ---------------------------------------------------------------------------
__device__ void tile_finish(int tile, int m0,
                            const float* __restrict__ b_dr,
                            const float* __restrict__ w_ih,
                            const float* __restrict__ b_ih) {
    extern __shared__ float dsm[];
    const int tid = threadIdx.x;
    const int tc  = tid & 31;
    const int tr  = tid >> 5;
    const int ar  = tid >> 1, ah = tid & 1;
    const uint32_t sbase = smem_u32(dsm);
    float* As = dsm;
    float* Bs = dsm + G1_BK * 128;

    const bool bval = tid < TH3;
    const float* bptr = w_ih + (size_t)(bval ? tid : 0) * R_;
    const size_t Q = (size_t)BT_ * R_;
    const float* part0 = &g_part[0][0];

    ull acc[8][8];
    #pragma unroll
    for (int p = 0; p < 8; p++)
        #pragma unroll
        for (int j = 0; j < 8; j++) acc[p][j] = 0ull;

    for (int c = 0; c < R_ / G1_BK; c++) {
        __syncthreads();
        // stage A: 8 xr values per thread = sum of 8 slabs + b_dr
        {
            const size_t base = (size_t)(m0 + ar) * R_ + c * G1_BK + ah * 8;
            float4 s0 = __ldcg((const float4*)(part0 + base));
            float4 s1 = __ldcg((const float4*)(part0 + base + 4));
            #pragma unroll
            for (int q = 1; q < KQ_; q++) {
                float4 v0 = __ldcg((const float4*)(part0 + q * Q + base));
                float4 v1 = __ldcg((const float4*)(part0 + q * Q + base + 4));
                s0.x += v0.x; s0.y += v0.y; s0.z += v0.z; s0.w += v0.w;
                s1.x += v1.x; s1.y += v1.y; s1.z += v1.z; s1.w += v1.w;
            }
            const float4 bd0 = __ldg((const float4*)(b_dr + c * G1_BK + ah * 8));
            const float4 bd1 = __ldg((const float4*)(b_dr + c * G1_BK + ah * 8 + 4));
            s0.x += bd0.x; s0.y += bd0.y; s0.z += bd0.z; s0.w += bd0.w;
            s1.x += bd1.x; s1.y += bd1.y; s1.z += bd1.z; s1.w += bd1.w;
            const int rb = ah * 8;
            As[(rb + 0) * 128 + ar] = s0.x; As[(rb + 1) * 128 + ar] = s0.y;
            As[(rb + 2) * 128 + ar] = s0.z; As[(rb + 3) * 128 + ar] = s0.w;
            As[(rb + 4) * 128 + ar] = s1.x; As[(rb + 5) * 128 + ar] = s1.y;
            As[(rb + 6) * 128 + ar] = s1.z; As[(rb + 7) * 128 + ar] = s1.w;
        }
        // stage B: 16 k-values of w_ih row tid
        if (bval) {
            const float* bp = bptr + c * G1_BK;
            const float4 b0 = *(const float4*)(bp + 0);
            const float4 b1 = *(const float4*)(bp + 4);
            const float4 b2 = *(const float4*)(bp + 8);
            const float4 b3 = *(const float4*)(bp + 12);
            const float bv[16] = {b0.x, b0.y, b0.z, b0.w, b1.x, b1.y, b1.z, b1.w,
                                  b2.x, b2.y, b2.z, b2.w, b3.x, b3.y, b3.z, b3.w};
            #pragma unroll
            for (int i = 0; i < 16; i++) Bs[i * 256 + tid] = bv[i];
        }
        __syncthreads();
        // compute chunk
        {
            const uint32_t sA = sbase + tr * 64;
            const float* BsP = Bs + tc * 8;
            #pragma unroll 4
            for (int k = 0; k < G1_BK; k++) {
                ull a[8];
                const uint32_t ab = sA + k * 512;
                asm("ld.shared.v2.b64 {%0,%1}, [%2];" : "=l"(a[0]), "=l"(a[1]) : "r"(ab));
                asm("ld.shared.v2.b64 {%0,%1}, [%2];" : "=l"(a[2]), "=l"(a[3]) : "r"(ab + 16));
                asm("ld.shared.v2.b64 {%0,%1}, [%2];" : "=l"(a[4]), "=l"(a[5]) : "r"(ab + 32));
                asm("ld.shared.v2.b64 {%0,%1}, [%2];" : "=l"(a[6]), "=l"(a[7]) : "r"(ab + 48));
                const float4 b0 = *(const float4*)(BsP + k * 256);
                const float4 b1 = *(const float4*)(BsP + k * 256 + 4);
                ull bd[8];
                bd[0] = dupf(b0.x); bd[1] = dupf(b0.y);
                bd[2] = dupf(b0.z); bd[3] = dupf(b0.w);
                bd[4] = dupf(b1.x); bd[5] = dupf(b1.y);
                bd[6] = dupf(b1.z); bd[7] = dupf(b1.w);
                #pragma unroll
                for (int p = 0; p < 8; p++)
                    #pragma unroll
                    for (int j = 0; j < 8; j++)
                        acc[p][j] = ffma2(a[p], bd[j], acc[p][j]);
            }
        }
    }

    // epilogue: write xp (cols < 216) with b_ih
    if (tc < 27) {
        const int n0 = tc * 8;
        const float4 bia0 = __ldg((const float4*)(b_ih + n0));
        const float4 bia1 = __ldg((const float4*)(b_ih + n0 + 4));
        #pragma unroll
        for (int p = 0; p < 8; p++) {
            const int r0 = m0 + tr * 16 + 2 * p;
            float4 lo0 = make_float4(f2lo(acc[p][0]) + bia0.x, f2lo(acc[p][1]) + bia0.y,
                                     f2lo(acc[p][2]) + bia0.z, f2lo(acc[p][3]) + bia0.w);
            float4 lo1 = make_float4(f2lo(acc[p][4]) + bia1.x, f2lo(acc[p][5]) + bia1.y,
                                     f2lo(acc[p][6]) + bia1.z, f2lo(acc[p][7]) + bia1.w);
            float4 hi0 = make_float4(f2hi(acc[p][0]) + bia0.x, f2hi(acc[p][1]) + bia0.y,
                                     f2hi(acc[p][2]) + bia0.z, f2hi(acc[p][3]) + bia0.w);
            float4 hi1 = make_float4(f2hi(acc[p][4]) + bia1.x, f2hi(acc[p][5]) + bia1.y,
                                     f2hi(acc[p][6]) + bia1.z, f2hi(acc[p][7]) + bia1.w);
            *(float4*)(g_xp + (size_t)r0 * TH3 + n0)           = lo0;
            *(float4*)(g_xp + (size_t)r0 * TH3 + n0 + 4)       = lo1;
            *(float4*)(g_xp + (size_t)(r0 + 1) * TH3 + n0)     = hi0;
            *(float4*)(g_xp + (size_t)(r0 + 1) * TH3 + n0 + 4) = hi1;
        }
    }
    __threadfence();
    __syncthreads();
    if (tid == 0) atomicExch(&g_flag[tile], 1u);
}

// ---------------------------------------------------------------------------
// producer branch: dynamic units off g_unit_ctr; wave-major order so
// each batch's tile-j completes before tile-j+1 across all batches.
// ---------------------------------------------------------------------------
__device__ void producer_branch(const float* __restrict__ A,
                                const float* __restrict__ Bw,
                                const float* __restrict__ b_dr,
                                const float* __restrict__ w_ih,
                                const float* __restrict__ b_ih) {
    extern __shared__ float dsm[];
    __shared__ unsigned int s_bcast;
    const int tid = threadIdx.x;
    const int tc  = tid & 31;
    const int tr  = tid >> 5;
    const int ar  = tid >> 1, ah = tid & 1;
    const uint32_t sbase = smem_u32(dsm);

    for (;;) {
        if (tid == 0) s_bcast = atomicAdd(&g_unit_ctr, 1u);
        __syncthreads();
        const unsigned int u = s_bcast;
        __syncthreads();
        if (u >= NUNITS) break;

        const int jw   = u >> 7;       // wave (tile-within-batch)
        const int rr   = u & 127;
        const int bb   = rr >> 3;      // batch
        const int kq   = rr & 7;       // k-slice
        const int tile = bb * 8 + jw;
        const int m0   = tile * 128;
        const size_t koff = (size_t)kq * (UCHUNK * G1_BK);

        // ---- partial unit (identical math to R12 gemm1) ----
        {
            ull acc[8][8];
            #pragma unroll
            for (int p = 0; p < 8; p++)
                #pragma unroll
                for (int j = 0; j < 8; j++) acc[p][j] = 0ull;

            const float* aptr = A + (size_t)(m0 + ar) * D_ + koff + ah * 8;
            const float* bptr = Bw + (size_t)tid * D_ + koff;

            float4 areg[2], breg[4];
            areg[0] = *(const float4*)(aptr + 0);
            areg[1] = *(const float4*)(aptr + 4);
            breg[0] = *(const float4*)(bptr + 0);
            breg[1] = *(const float4*)(bptr + 4);
            breg[2] = *(const float4*)(bptr + 8);
            breg[3] = *(const float4*)(bptr + 12);
            {
                float* As = dsm;
                float* Bs = dsm + G1_BK * 128;
                const float av[8] = {areg[0].x, areg[0].y, areg[0].z, areg[0].w,
                                     areg[1].x, areg[1].y, areg[1].z, areg[1].w};
                #pragma unroll
                for (int i = 0; i < 8; i++) As[(ah * 8 + i) * 128 + ar] = av[i];
                const float bv[16] = {breg[0].x, breg[0].y, breg[0].z, breg[0].w,
                                      breg[1].x, breg[1].y, breg[1].z, breg[1].w,
                                      breg[2].x, breg[2].y, breg[2].z, breg[2].w,
                                      breg[3].x, breg[3].y, breg[3].z, breg[3].w};
                #pragma unroll
                for (int i = 0; i < 16; i++) Bs[i * 256 + tid] = bv[i];
            }
            __syncthreads();

            for (int c = 0; c < UCHUNK; c++) {
                const int s = c & 1;
                if (c + 1 < UCHUNK) {
                    const float* ap = aptr + (size_t)(c + 1) * G1_BK;
                    const float* bp = bptr + (size_t)(c + 1) * G1_BK;
                    areg[0] = *(const float4*)(ap + 0);
                    areg[1] = *(const float4*)(ap + 4);
                    breg[0] = *(const float4*)(bp + 0);
                    breg[1] = *(const float4*)(bp + 4);
                    breg[2] = *(const float4*)(bp + 8);
                    breg[3] = *(const float4*)(bp + 12);
                }
                {
                    const uint32_t sA = sbase + s * G1_STAGE_BYTES + tr * 64;
                    const float*  Bs = dsm + s * G1_STAGE_FLOATS + G1_BK * 128 + tc * 8;
                    #pragma unroll 4
                    for (int k = 0; k < G1_BK; k++) {
                        ull a[8];
                        const uint32_t ab = sA + k * 512;
                        asm("ld.shared.v2.b64 {%0,%1}, [%2];" : "=l"(a[0]), "=l"(a[1]) : "r"(ab));
                        asm("ld.shared.v2.b64 {%0,%1}, [%2];" : "=l"(a[2]), "=l"(a[3]) : "r"(ab + 16));
                        asm("ld.shared.v2.b64 {%0,%1}, [%2];" : "=l"(a[4]), "=l"(a[5]) : "r"(ab + 32));
                        asm("ld.shared.v2.b64 {%0,%1}, [%2];" : "=l"(a[6]), "=l"(a[7]) : "r"(ab + 48));
                        const float4 b0 = *(const float4*)(Bs + k * 256);
                        const float4 b1 = *(const float4*)(Bs + k * 256 + 4);
                        ull bd[8];
                        bd[0] = dupf(b0.x); bd[1] = dupf(b0.y);
                        bd[2] = dupf(b0.z); bd[3] = dupf(b0.w);
                        bd[4] = dupf(b1.x); bd[5] = dupf(b1.y);
                        bd[6] = dupf(b1.z); bd[7] = dupf(b1.w);
                        #pragma unroll
                        for (int p = 0; p < 8; p++)
                            #pragma unroll
                            for (int j = 0; j < 8; j++)
                                acc[p][j] = ffma2(a[p], bd[j], acc[p][j]);
                    }
                }
                if (c + 1 < UCHUNK) {
                    float* As = dsm + (s ^ 1) * G1_STAGE_FLOATS;
                    float* Bs = As + G1_BK * 128;
                    const float av[8] = {areg[0].x, areg[0].y, areg[0].z, areg[0].w,
                                         areg[1].x, areg[1].y, areg[1].z, areg[1].w};
                    #pragma unroll
                    for (int i = 0; i < 8; i++) As[(ah * 8 + i) * 128 + ar] = av[i];
                    const float bv[16] = {breg[0].x, breg[0].y, breg[0].z, breg[0].w,
                                          breg[1].x, breg[1].y, breg[1].z, breg[1].w,
                                          breg[2].x, breg[2].y, breg[2].z, breg[2].w,
                                          breg[3].x, breg[3].y, breg[3].z, breg[3].w};
                    #pragma unroll
                    for (int i = 0; i < 16; i++) Bs[i * 256 + tid] = bv[i];
                }
                __syncthreads();
            }

            float* Cp = &g_part[kq][0];
            const int n0 = tc * 8;
            #pragma unroll
            for (int p = 0; p < 8; p++) {
                const int r0 = m0 + tr * 16 + 2 * p;
                float4 lo0 = make_float4(f2lo(acc[p][0]), f2lo(acc[p][1]),
                                         f2lo(acc[p][2]), f2lo(acc[p][3]));
                float4 lo1 = make_float4(f2lo(acc[p][4]), f2lo(acc[p][5]),
                                         f2lo(acc[p][6]), f2lo(acc[p][7]));
                float4 hi0 = make_float4(f2hi(acc[p][0]), f2hi(acc[p][1]),
                                         f2hi(acc[p][2]), f2hi(acc[p][3]));
                float4 hi1 = make_float4(f2hi(acc[p][4]), f2hi(acc[p][5]),
                                         f2hi(acc[p][6]), f2hi(acc[p][7]));
                *(float4*)(Cp + (size_t)r0 * R_ + n0)           = lo0;
                *(float4*)(Cp + (size_t)r0 * R_ + n0 + 4)       = lo1;
                *(float4*)(Cp + (size_t)(r0 + 1) * R_ + n0)     = hi0;
                *(float4*)(Cp + (size_t)(r0 + 1) * R_ + n0 + 4) = hi1;
            }
        }

        // ---- count; 8th unit runs the tile finish ----
        __threadfence();
        __syncthreads();
        if (tid == 0) s_bcast = atomicAdd(&g_cnt[tile], 1u);
        __syncthreads();
        const unsigned int old = s_bcast;
        __syncthreads();
        if (old == 7u) {
            __threadfence();
            tile_finish(tile, m0, b_dr, w_ih, b_ih);
        }
    }
}

// ---------------------------------------------------------------------------
// GRU branch: R12 structure + per-tile flag gating (streams xp as produced)
// ---------------------------------------------------------------------------
__device__ void gru_branch(int b,
                           const float* __restrict__ w_hh,
                           const float* __restrict__ b_hh) {
    __shared__ __align__(16) float h[H_];
    __shared__ float hp[TH3];
    __shared__ float xv[TH3];

    const int j = threadIdx.x;

    ull w2[36];
    ull bh2 = 0ull;
    if (j < TH3) {
        #pragma unroll
        for (int i = 0; i < 36; i++)
            w2[i] = packf(w_hh[j * H_ + 2 * i], w_hh[j * H_ + 2 * i + 1]);
        bh2 = packf(b_hh[j], 0.f);
    }
    if (j < H_) h[j] = 0.f;

    const uint32_t hb = smem_u32(h);
    const float* xprow = g_xp + (size_t)b * T_ * TH3;
    float* hrow = g_hseq + (size_t)b * T_ * H_;

    wait_flag(&g_flag[b * 8]);          // tile 0 ready (also syncs h init)
    float xpv0 = (j < TH3) ? __ldcg(xprow + j) : 0.f;
    float xpv1 = (j < TH3) ? __ldcg(xprow + TH3 + j) : 0.f;
    __syncthreads();

    for (int t = 0; t < T_; t++) {
        // gate the t+2 prefetch on its tile's flag (uniform condition)
        if (((t + 2) & 127) == 0 && (t + 2) < T_)
            wait_flag(&g_flag[b * 8 + ((t + 2) >> 7)]);

        if (j < TH3) {
            ull a0 = bh2, a1 = 0ull, a2 = 0ull, a3 = 0ull;
            #pragma unroll
            for (int i = 0; i < 18; i++) {
                ull p0, p1;
                asm volatile("ld.shared.v2.b64 {%0,%1}, [%2];"
                             : "=l"(p0), "=l"(p1) : "r"(hb + i * 16));
                if (i & 1) {
                    a2 = ffma2(w2[2 * i],     p0, a2);
                    a3 = ffma2(w2[2 * i + 1], p1, a3);
                } else {
                    a0 = ffma2(w2[2 * i],     p0, a0);
                    a1 = ffma2(w2[2 * i + 1], p1, a1);
                }
            }
            ull s = fadd2(fadd2(a0, a2), fadd2(a1, a3));
            hp[j] = f2lo(s) + f2hi(s);
            xv[j] = xpv0;
        }
        float xnext = 0.f;
        if (j < TH3 && t + 2 < T_) xnext = __ldcg(xprow + (size_t)(t + 2) * TH3 + j);
        __syncthreads();

        if (j < H_) {
            float r  = __fdividef(1.f, 1.f + __expf(-(xv[j]        + hp[j])));
            float z  = __fdividef(1.f, 1.f + __expf(-(xv[j + H_]   + hp[j + H_])));
            float n  = tanh_fast(xv[j + 2 * H_] + r * hp[j + 2 * H_]);
            float hn = (1.f - z) * n + z * h[j];
            h[j] = hn;
            hrow[(size_t)t * H_ + j] = hn;
        }
        __syncthreads();

        xpv0 = xpv1;
        xpv1 = xnext;
    }
}

// ---------------------------------------------------------------------------
// mega kernel: CTAs 0-15 = GRU consumers, 16-147 = producers
// ---------------------------------------------------------------------------
__global__ __launch_bounds__(256, 1)
void mega_kernel(const float* __restrict__ x,
                 const float* __restrict__ w_dr,
                 const float* __restrict__ b_dr,
                 const float* __restrict__ w_ih,
                 const float* __restrict__ b_ih,
                 const float* __restrict__ w_hh,
                 const float* __restrict__ b_hh) {
    if (blockIdx.x < 16) gru_branch(blockIdx.x, w_hh, b_hh);
    else                 producer_branch(x, w_dr, b_dr, w_ih, b_ih);
}

// ---------------------------------------------------------------------------
// q[b,t] = dot(hseq[b,t,:], w_reg) + b_reg
// ---------------------------------------------------------------------------
__global__ __launch_bounds__(128)
void qgemv_kernel(const float* __restrict__ hseq,
                  const float* __restrict__ w_reg,
                  const float* __restrict__ b_reg,
                  float* __restrict__ q)
{
    __shared__ float sh[128 * 73];
    __shared__ float swr[H_];

    const int tid  = threadIdx.x;
    const int row0 = blockIdx.x * 128;

    const float4* src = (const float4*)(hseq + (size_t)row0 * H_);
    for (int i = tid; i < 128 * (H_ / 4); i += 128) {
        const int r  = i / (H_ / 4);
        const int c4 = i - r * (H_ / 4);
        float4 v = src[i];
        float* d = &sh[r * 73 + c4 * 4];
        d[0] = v.x; d[1] = v.y; d[2] = v.z; d[3] = v.w;
    }
    if (tid < H_) swr[tid] = w_reg[tid];
    __syncthreads();

    float acc = b_reg[0];
    const float* hr = &sh[tid * 73];
    #pragma unroll
    for (int i = 0; i < H_; i++) acc = fmaf(hr[i], swr[i], acc);
    q[row0 + tid] = acc;
}

// ---------------------------------------------------------------------------
// sitp + sigmoid heads
// ---------------------------------------------------------------------------
__global__ __launch_bounds__(1024, 1)
void sitp_kernel(const float* __restrict__ q,
                 const int*   __restrict__ xlen,
                 const float* __restrict__ nlm_w1, const float* __restrict__ nlm_b1,
                 const float* __restrict__ nlm_w2, const float* __restrict__ nlm_b2,
                 const float* __restrict__ lm_w,   const float* __restrict__ lm_b,
                 float* __restrict__ out)
{
    const int b = blockIdx.x;
    const int t = threadIdx.x;

    __shared__ float qs[T_];
    __shared__ float ws[T_];
    __shared__ float wqs[T_];
    __shared__ float warpsum[32];

    const int len = xlen[b];
    const float qv = q[b * T_ + t];
    const bool valid = t < len;

    qs[t] = qv;
    const float wv = valid ? expf(-qv) : 0.f;
    ws[t]  = wv;
    wqs[t] = wv * qv;
    __syncthreads();

    float c = 0.f;
    if (valid) {
        float xmin = qv;
        #pragma unroll
        for (int d = 1; d < TAU; d++) {
            int s = t - d;
            if (s >= 0) xmin = fminf(xmin, qs[s]);
        }
        float num = 0.f, den = 0.f;
        #pragma unroll
        for (int d = 0; d < TAU; d++) {
            int s = t + d;
            if (s < T_) { num += wqs[s]; den += ws[s]; }
        }
        float y = (den > 0.f) ? num / fmaxf(den, 1e-30f) : 0.f;
        c = 0.5f * y + 0.5f * xmin;
    }

    #pragma unroll
    for (int off = 16; off > 0; off >>= 1)
        c += __shfl_down_sync(0xFFFFFFFFu, c, off);
    const int wid  = t >> 5;
    const int lane = t & 31;
    if (lane == 0) warpsum[wid] = c;
    __syncthreads();
    if (wid == 0) {
        float v = warpsum[lane];
        #pragma unroll
        for (int off = 16; off > 0; off >>= 1)
            v += __shfl_down_sync(0xFFFFFFFFu, v, off);
        if (lane == 0) {
            const float s        = v / (float)len;
            const float relative = 1.f / (1.f + expf(-s));
            const float mapped   = (1.f / (1.f + expf(-(nlm_w1[0] * relative + nlm_b1[0]))))
                                   * nlm_w2[0] + nlm_b2[0];
            const float aligned  = lm_w[0] * mapped + lm_b[0];
            out[b]          = relative;
            out[B_ + b]     = mapped;
            out[2 * B_ + b] = aligned;
        }
    }
}

// ---------------------------------------------------------------------------
// Launch
// ---------------------------------------------------------------------------
extern "C" void kernel_launch(void* const* d_in, const int* in_sizes, int n_in,
                              void* d_out, int out_size)
{
    const float* x     = (const float*)d_in[0];
    const int*   x_len = (const int*)  d_in[1];
    const float* w_dr  = (const float*)d_in[2];
    const float* b_dr  = (const float*)d_in[3];
    const float* w_ih  = (const float*)d_in[4];
    const float* w_hh  = (const float*)d_in[5];
    const float* b_ih  = (const float*)d_in[6];
    const float* b_hh  = (const float*)d_in[7];
    const float* w_reg = (const float*)d_in[8];
    const float* b_reg = (const float*)d_in[9];
    const float* nlm_w1 = (const float*)d_in[10];
    const float* nlm_b1 = (const float*)d_in[11];
    const float* nlm_w2 = (const float*)d_in[12];
    const float* nlm_b2 = (const float*)d_in[13];
    const float* lm_w   = (const float*)d_in[14];
    const float* lm_b   = (const float*)d_in[15];
    float* out = (float*)d_out;

    float* hs;   cudaGetSymbolAddress((void**)&hs,   g_hseq);
    float* qq;   cudaGetSymbolAddress((void**)&qq,   g_q);

    static bool attr_done = false;
    if (!attr_done) {
        cudaFuncSetAttribute(mega_kernel,
                             cudaFuncAttributeMaxDynamicSharedMemorySize, G1_DYN);
        attr_done = true;
    }

    // reset flags/counters (graph replays)
    init_kernel<<<1, 128>>>();
    // fused producer/consumer: GEMM1 partials + per-tile reduce+GEMM2 + GRU
    mega_kernel<<<GRID_MEGA, 256, G1_DYN>>>(x, w_dr, b_dr, w_ih, b_ih, w_hh, b_hh);
    // q = hseq @ w_reg + b_reg
    qgemv_kernel<<<BT_ / 128, 128>>>(hs, w_reg, b_reg, qq);
    // sitp windows + heads
    sitp_kernel<<<B_, T_>>>(qq, x_len, nlm_w1, nlm_b1, nlm_w2, nlm_b2,
                            lm_w, lm_b, out);
}